// round 15
// baseline (speedup 1.0000x reference)
#include <cuda_runtime.h>

#define BB   4
#define NN   256
#define OBSD 40
#define TT   256
#define DIMG 32
#define HEADG 8
#define ACTD 8

__device__ float g_EMB[BB * NN * TT];
__device__ float g_NEp[2][BB * NN * TT];
__device__ float g_CSp[2 * BB * 2 * NN * TT];   // [s][b][w]
__device__ float g_sumNH[BB * TT];
__device__ float g_sumHID[BB * TT];
__device__ unsigned g_cnt[BB];

// ---------------------------------------------------------------------------
// 32x64 output tile, 128 threads (8x16), 4x4 micro-tile, double-buffered
// k-tiles of 16 (measured-best shape, R6/R11).
// ---------------------------------------------------------------------------
template <class FA, class FB>
__device__ __forceinline__ void mm32x64(FA ldA, FB ldB, int nkt,
                                        float acc[4][4], int tid,
                                        float As[2][16][36], float Bs[2][16][68])
{
    const int ty = tid >> 4, tx = tid & 15;
    {
#pragma unroll
        for (int i = 0; i < 4; ++i) {
            int idx = tid + i * 128;
            As[0][idx & 15][idx >> 4] = ldA(0, idx >> 4, idx & 15);
        }
#pragma unroll
        for (int i = 0; i < 8; ++i) {
            int idx = tid + i * 128;
            Bs[0][idx >> 6][idx & 63] = ldB(0, idx >> 6, idx & 63);
        }
    }
    __syncthreads();
    for (int t = 0; t < nkt; ++t) {
        float ra[4], rb[8];
        if (t + 1 < nkt) {
#pragma unroll
            for (int i = 0; i < 4; ++i) {
                int idx = tid + i * 128;
                ra[i] = ldA(t + 1, idx >> 4, idx & 15);
            }
#pragma unroll
            for (int i = 0; i < 8; ++i) {
                int idx = tid + i * 128;
                rb[i] = ldB(t + 1, idx >> 6, idx & 63);
            }
        }
        int buf = t & 1;
#pragma unroll
        for (int k = 0; k < 16; ++k) {
            float a[4], b[4];
            *(float4*)a = *(const float4*)&As[buf][k][ty * 4];
            *(float4*)b = *(const float4*)&Bs[buf][k][tx * 4];
#pragma unroll
            for (int i = 0; i < 4; ++i)
#pragma unroll
                for (int j = 0; j < 4; ++j) acc[i][j] = fmaf(a[i], b[j], acc[i][j]);
        }
        if (t + 1 < nkt) {
            int nb = buf ^ 1;
#pragma unroll
            for (int i = 0; i < 4; ++i) {
                int idx = tid + i * 128;
                As[nb][idx & 15][idx >> 4] = ra[i];
            }
#pragma unroll
            for (int i = 0; i < 8; ++i) {
                int idx = tid + i * 128;
                Bs[nb][idx >> 6][idx & 63] = rb[i];
            }
            __syncthreads();
        }
    }
}

// ---------------------------------------------------------------------------
// K1: fused h1 + emb. grid (32,4) = 128 blocks, 128 thr.
// Stage A: compute the block's 32-row H1 strip (all 256 cols) into smem
// (4x redundant across the 4 emb col-tiles; H1 FMA is cheap).
// Stage B: EMB tile = relu(H1strip @ We2[:,c0:c0+64] + be2), K=256 from smem.
// Writes g_EMB FINAL (no partials anywhere downstream). Zeroes sums+counters.
// ---------------------------------------------------------------------------
__global__ void __launch_bounds__(128)
h1emb_kernel(const float* __restrict__ x,
             const float* __restrict__ We1, const float* __restrict__ be1,
             const float* __restrict__ We2, const float* __restrict__ be2)
{
    __shared__ float H1s[32][260];        // 33.3 KB
    __shared__ float As[2][16][36];       // 4.6 KB
    __shared__ float Bs[2][16][68];       // 8.7 KB
    const int r0 = blockIdx.x * 32;
    const int c0 = blockIdx.y * 64;
    const int tid = threadIdx.x, ty = tid >> 4, tx = tid & 15;

    if (blockIdx.x == 0 && blockIdx.y == 0) {
        for (int i = tid; i < BB * TT; i += 128) {
            g_sumNH[i] = 0.f;
            g_sumHID[i] = 0.f;
        }
        if (tid < BB) g_cnt[tid] = 0u;
    }

    // ---- Stage A: H1 strip, 4 col-chunks of 64 ----
    for (int cc = 0; cc < 4; ++cc) {
        float acc[4][4] = {};
        mm32x64(
            [&](int kt, int r, int k) {
                int kg = kt * 16 + k;
                int row = r0 + r, b = row >> 8, n = row & 255;
                return (kg < OBSD) ? x[b * ((NN + 1) * OBSD) + n * OBSD + kg] : 0.f;
            },
            [&](int kt, int kk, int c) {
                int kg = kt * 16 + kk;
                return (kg < OBSD) ? We1[kg * TT + cc * 64 + c] : 0.f;
            },
            3, acc, tid, As, Bs);
        __syncthreads();   // all reads of As/Bs done before next stage reuses them
#pragma unroll
        for (int i = 0; i < 4; ++i)
#pragma unroll
            for (int j = 0; j < 4; ++j) {
                int c = cc * 64 + tx * 4 + j;
                H1s[ty * 4 + i][c] = fmaxf(acc[i][j] + be1[c], 0.f);
            }
        __syncthreads();
    }

    // ---- Stage B: EMB tile, K=256 from H1s ----
    float acc[4][4] = {};
    mm32x64(
        [&](int kt, int r, int k) { return H1s[r][kt * 16 + k]; },
        [&](int kt, int kk, int c) { return We2[(kt * 16 + kk) * TT + c0 + c]; },
        16, acc, tid, As, Bs);

#pragma unroll
    for (int i = 0; i < 4; ++i)
#pragma unroll
        for (int j = 0; j < 4; ++j) {
            int c = c0 + tx * 4 + j;
            g_EMB[(r0 + ty * 4 + i) * TT + c] = fmaxf(acc[i][j] + be2[c], 0.f);
        }
}

// ---------------------------------------------------------------------------
// K2: NEp[s][b] = adj @ EMB[b] over K-half s (EMB read directly).
// grid (8,4,8) = 256 blocks, z = b*2+s.
// ---------------------------------------------------------------------------
__global__ void __launch_bounds__(128)
ne_kernel(const float* __restrict__ adj)
{
    __shared__ float As[2][16][36];
    __shared__ float Bs[2][16][68];
    const int b = blockIdx.z >> 1;
    const int s = blockIdx.z & 1;
    const int kb = s * 128;
    const int r0 = blockIdx.x * 32;
    const int c0 = blockIdx.y * 64;
    const int ebase = b * (NN * TT);
    const int tid = threadIdx.x, ty = tid >> 4, tx = tid & 15;

    float acc[4][4] = {};
    mm32x64(
        [&](int kt, int r, int k) { return adj[(r0 + r) * NN + kb + kt * 16 + k]; },
        [&](int kt, int kk, int c) {
            return g_EMB[ebase + (kb + kt * 16 + kk) * TT + c0 + c];
        },
        8, acc, tid, As, Bs);

    float* C = &g_NEp[s][ebase];
#pragma unroll
    for (int i = 0; i < 4; ++i)
#pragma unroll
        for (int j = 0; j < 4; ++j)
            C[(r0 + ty * 4 + i) * TT + c0 + tx * 4 + j] = acc[i][j];
}

// ---------------------------------------------------------------------------
// K3: CSp[s][b][w] = NE[b] @ W_w over K-half s (pre-relu partial GEMM).
// NE = NEp0+NEp1 on A-load. grid (8,4,16) = 512 blocks (R11's 14.9us config).
// ---------------------------------------------------------------------------
__global__ void __launch_bounds__(128)
colsum_gemm_kernel(const float* __restrict__ Wn, const float* __restrict__ Wh)
{
    __shared__ float As[2][16][36];
    __shared__ float Bs[2][16][68];
    const int s = blockIdx.z & 1;
    const int w = (blockIdx.z >> 1) & 1;
    const int b = blockIdx.z >> 2;
    const int kb = s * 128;
    const int r0 = blockIdx.x * 32;
    const int c0 = blockIdx.y * 64;
    const int abase = b * (NN * TT);
    const float* W = (w ? Wh : Wn) + c0;
    const int tid = threadIdx.x, ty = tid >> 4, tx = tid & 15;

    float acc[4][4] = {};
    mm32x64(
        [&](int kt, int r, int k) {
            int ai = abase + (r0 + r) * TT + kb + kt * 16 + k;
            return g_NEp[0][ai] + g_NEp[1][ai];
        },
        [&](int kt, int kk, int c) { return W[(kb + kt * 16 + kk) * TT + c]; },
        8, acc, tid, As, Bs);

    float* C = &g_CSp[(((s * BB) + b) * 2 + w) * (NN * TT)];
#pragma unroll
    for (int i = 0; i < 4; ++i)
#pragma unroll
        for (int j = 0; j < 4; ++j)
            C[(r0 + ty * 4 + i) * TT + c0 + tx * 4 + j] = acc[i][j];
}

// ---------------------------------------------------------------------------
// K4: fused combine + epilogue. grid (4 batch, 8 part), 256 thr.
// Part p: w=p&1, cq=p>>1. Block sums its 64 cols over 256 rows of
// relu(P0+P1+bias) into the sums; LAST block per batch (fence+counter)
// runs the epilogue. Slab pointers include (s,b,w); index = row*TT+col.
// ---------------------------------------------------------------------------
__global__ void __launch_bounds__(256)
final_kernel(const float* __restrict__ x,
             const float* __restrict__ bn, const float* __restrict__ bh,
             const float* __restrict__ Wl, const float* __restrict__ bl,
             const float* __restrict__ Wa, const float* __restrict__ ba,
             float* __restrict__ out)
{
    __shared__ unsigned s_ret;
    const int b = blockIdx.x;
    const int p = blockIdx.y;
    const int w = p & 1;
    const int cq = p >> 1;
    const int t = threadIdx.x;

    {
        const int col = cq * 64 + (t & 63);
        const int rs = (t >> 6) * 64;
        const float bv = (w ? bh : bn)[col];
        const float* P0 = &g_CSp[(((0 * BB) + b) * 2 + w) * (NN * TT)];
        const float* P1 = &g_CSp[(((1 * BB) + b) * 2 + w) * (NN * TT)];
        float s = 0.f;
#pragma unroll 4
        for (int r = 0; r < 64; ++r) {
            int idx = (rs + r) * TT + col;
            s += fmaxf(P0[idx] + P1[idx] + bv, 0.f);
        }
        float* dst = (w ? g_sumHID : g_sumNH);
        atomicAdd(&dst[b * TT + col], s);
    }

    __threadfence();
    __syncthreads();
    if (t == 0) s_ret = atomicAdd(&g_cnt[b], 1u);
    __syncthreads();
    if (s_ret != 7u) return;
    __threadfence();

    // ---- epilogue for batch b ----
    __shared__ float er[256];
    __shared__ float av[256];
    __shared__ float prod[256];
    __shared__ float mx[8], sm[8];
    __shared__ float od[32];

    const int tgt = (int)x[b * ((NN + 1) * OBSD) + NN * OBSD];
    er[t] = g_EMB[(b * NN + tgt) * TT + t];
    __syncthreads();

    float acc = bl[t];
#pragma unroll 8
    for (int k = 0; k < TT; ++k) acc = fmaf(er[k], Wl[k * TT + t], acc);
    float l = fmaxf(acc, 0.f);
    av[t] = l * g_sumNH[b * TT + t];
    __syncthreads();

    if (t < HEADG) {
        float m = -1e30f;
        for (int d = 0; d < DIMG; ++d) m = fmaxf(m, av[d * HEADG + t]);
        float s = 0.f;
        for (int d = 0; d < DIMG; ++d) s += __expf(av[d * HEADG + t] - m);
        mx[t] = m; sm[t] = s;
    }
    __syncthreads();

    int h = t & (HEADG - 1);
    float attn = __expf(av[t] - mx[h]) / sm[h];
    prod[t] = attn * g_sumHID[b * TT + t];
    __syncthreads();

    if (t < DIMG) {
        float s = 0.f;
#pragma unroll
        for (int hh = 0; hh < HEADG; ++hh) s += prod[t * HEADG + hh];
        od[t] = s * (1.0f / HEADG);
    }
    __syncthreads();

    if (t < ACTD) {
        float a = ba[t];
#pragma unroll
        for (int d = 0; d < DIMG; ++d) a = fmaf(od[d], Wa[d * ACTD + t], a);
        out[b * ACTD + t] = a;
    }
}

// ---------------------------------------------------------------------------
extern "C" void kernel_launch(void* const* d_in, const int* in_sizes, int n_in,
                              void* d_out, int out_size)
{
    const float* x   = (const float*)d_in[0];
    const float* adj = (const float*)d_in[1];
    const float* We1 = (const float*)d_in[2];
    const float* be1 = (const float*)d_in[3];
    const float* We2 = (const float*)d_in[4];
    const float* be2 = (const float*)d_in[5];
    const float* Wl  = (const float*)d_in[6];
    const float* bl  = (const float*)d_in[7];
    const float* Wn  = (const float*)d_in[8];
    const float* bn  = (const float*)d_in[9];
    const float* Wh  = (const float*)d_in[10];
    const float* bh  = (const float*)d_in[11];
    const float* Wa  = (const float*)d_in[12];
    const float* ba  = (const float*)d_in[13];
    float* out = (float*)d_out;

    h1emb_kernel<<<dim3(32, 4), 128>>>(x, We1, be1, We2, be2);
    ne_kernel<<<dim3(8, 4, 8), 128>>>(adj);
    colsum_gemm_kernel<<<dim3(8, 4, 16), 128>>>(Wn, Wh);
    final_kernel<<<dim3(BB, 8), 256>>>(x, bn, bh, Wl, bl, Wa, ba, out);
}

// round 16
// speedup vs baseline: 1.2134x; 1.2134x over previous
#include <cuda_runtime.h>

#define BB   4
#define NN   256
#define OBSD 40
#define TT   256
#define DIMG 32
#define HEADG 8
#define ACTD 8

__device__ float g_EMB[BB * NN * TT];
__device__ float g_NEp[2][BB * NN * TT];
__device__ float g_CSp[2 * BB * 2 * NN * TT];   // [s][b][w]
__device__ float g_lvec[BB * TT];
__device__ float g_sumNH[BB * TT];
__device__ float g_sumHID[BB * TT];
__device__ unsigned g_cnt[BB];

// ---------------------------------------------------------------------------
// 32x64 output tile, 128 threads (8x16), 4x4 micro-tile, double-buffered
// k-tiles of 16 (measured-best shape, R6/R11).
// ---------------------------------------------------------------------------
template <class FA, class FB>
__device__ __forceinline__ void mm32x64(FA ldA, FB ldB, int nkt,
                                        float acc[4][4], int tid,
                                        float As[2][16][36], float Bs[2][16][68])
{
    const int ty = tid >> 4, tx = tid & 15;
    {
#pragma unroll
        for (int i = 0; i < 4; ++i) {
            int idx = tid + i * 128;
            As[0][idx & 15][idx >> 4] = ldA(0, idx >> 4, idx & 15);
        }
#pragma unroll
        for (int i = 0; i < 8; ++i) {
            int idx = tid + i * 128;
            Bs[0][idx >> 6][idx & 63] = ldB(0, idx >> 6, idx & 63);
        }
    }
    __syncthreads();
    for (int t = 0; t < nkt; ++t) {
        float ra[4], rb[8];
        if (t + 1 < nkt) {
#pragma unroll
            for (int i = 0; i < 4; ++i) {
                int idx = tid + i * 128;
                ra[i] = ldA(t + 1, idx >> 4, idx & 15);
            }
#pragma unroll
            for (int i = 0; i < 8; ++i) {
                int idx = tid + i * 128;
                rb[i] = ldB(t + 1, idx >> 6, idx & 63);
            }
        }
        int buf = t & 1;
#pragma unroll
        for (int k = 0; k < 16; ++k) {
            float a[4], b[4];
            *(float4*)a = *(const float4*)&As[buf][k][ty * 4];
            *(float4*)b = *(const float4*)&Bs[buf][k][tx * 4];
#pragma unroll
            for (int i = 0; i < 4; ++i)
#pragma unroll
                for (int j = 0; j < 4; ++j) acc[i][j] = fmaf(a[i], b[j], acc[i][j]);
        }
        if (t + 1 < nkt) {
            int nb = buf ^ 1;
#pragma unroll
            for (int i = 0; i < 4; ++i) {
                int idx = tid + i * 128;
                As[nb][idx & 15][idx >> 4] = ra[i];
            }
#pragma unroll
            for (int i = 0; i < 8; ++i) {
                int idx = tid + i * 128;
                Bs[nb][idx >> 6][idx & 63] = rb[i];
            }
            __syncthreads();
        }
    }
}

// ---------------------------------------------------------------------------
// K1: fused h1 + emb. grid (32,4) = 128 blocks, 128 thr.
// Stage A: block's 32-row H1 strip into smem (4x redundant, cheap).
// Stage B: EMB tile = relu(H1strip @ We2 + be2), K=256 from smem.
// Writes g_EMB final. Zeroes sums + counters.
// ---------------------------------------------------------------------------
__global__ void __launch_bounds__(128)
h1emb_kernel(const float* __restrict__ x,
             const float* __restrict__ We1, const float* __restrict__ be1,
             const float* __restrict__ We2, const float* __restrict__ be2)
{
    __shared__ float H1s[32][260];
    __shared__ float As[2][16][36];
    __shared__ float Bs[2][16][68];
    const int r0 = blockIdx.x * 32;
    const int c0 = blockIdx.y * 64;
    const int tid = threadIdx.x, ty = tid >> 4, tx = tid & 15;

    if (blockIdx.x == 0 && blockIdx.y == 0) {
        for (int i = tid; i < BB * TT; i += 128) {
            g_sumNH[i] = 0.f;
            g_sumHID[i] = 0.f;
        }
        if (tid < BB) g_cnt[tid] = 0u;
    }

    for (int cc = 0; cc < 4; ++cc) {
        float acc[4][4] = {};
        mm32x64(
            [&](int kt, int r, int k) {
                int kg = kt * 16 + k;
                int row = r0 + r, b = row >> 8, n = row & 255;
                return (kg < OBSD) ? x[b * ((NN + 1) * OBSD) + n * OBSD + kg] : 0.f;
            },
            [&](int kt, int kk, int c) {
                int kg = kt * 16 + kk;
                return (kg < OBSD) ? We1[kg * TT + cc * 64 + c] : 0.f;
            },
            3, acc, tid, As, Bs);
        __syncthreads();
#pragma unroll
        for (int i = 0; i < 4; ++i)
#pragma unroll
            for (int j = 0; j < 4; ++j) {
                int c = cc * 64 + tx * 4 + j;
                H1s[ty * 4 + i][c] = fmaxf(acc[i][j] + be1[c], 0.f);
            }
        __syncthreads();
    }

    float acc[4][4] = {};
    mm32x64(
        [&](int kt, int r, int k) { return H1s[r][kt * 16 + k]; },
        [&](int kt, int kk, int c) { return We2[(kt * 16 + kk) * TT + c0 + c]; },
        16, acc, tid, As, Bs);

#pragma unroll
    for (int i = 0; i < 4; ++i)
#pragma unroll
        for (int j = 0; j < 4; ++j) {
            int c = c0 + tx * 4 + j;
            g_EMB[(r0 + ty * 4 + i) * TT + c] = fmaxf(acc[i][j] + be2[c], 0.f);
        }
}

// ---------------------------------------------------------------------------
// K2: NEp[s][b] = adj @ EMB[b] over K-half s. grid (8,4,8) = 256 blocks.
// ---------------------------------------------------------------------------
__global__ void __launch_bounds__(128)
ne_kernel(const float* __restrict__ adj)
{
    __shared__ float As[2][16][36];
    __shared__ float Bs[2][16][68];
    const int b = blockIdx.z >> 1;
    const int s = blockIdx.z & 1;
    const int kb = s * 128;
    const int r0 = blockIdx.x * 32;
    const int c0 = blockIdx.y * 64;
    const int ebase = b * (NN * TT);
    const int tid = threadIdx.x, ty = tid >> 4, tx = tid & 15;

    float acc[4][4] = {};
    mm32x64(
        [&](int kt, int r, int k) { return adj[(r0 + r) * NN + kb + kt * 16 + k]; },
        [&](int kt, int kk, int c) {
            return g_EMB[ebase + (kb + kt * 16 + kk) * TT + c0 + c];
        },
        8, acc, tid, As, Bs);

    float* C = &g_NEp[s][ebase];
#pragma unroll
    for (int i = 0; i < 4; ++i)
#pragma unroll
        for (int j = 0; j < 4; ++j)
            C[(r0 + ty * 4 + i) * TT + c0 + tx * 4 + j] = acc[i][j];
}

// ---------------------------------------------------------------------------
// K3: z<16: CSp[s][b][w] = NE[b] @ W_w over K-half s (512 blocks, the
// measured-best colsum shape). z==16: 32 extra blocks compute the per-batch
// l-vector GEMV l[b] = relu(emb[b,tgt] @ Wl + bl) — independent of colsum,
// hidden under it. grid (8,4,17).
// ---------------------------------------------------------------------------
__global__ void __launch_bounds__(128)
colsum_gemm_kernel(const float* __restrict__ Wn, const float* __restrict__ Wh,
                   const float* __restrict__ x,
                   const float* __restrict__ Wl, const float* __restrict__ bl)
{
    __shared__ float As[2][16][36];
    __shared__ float Bs[2][16][68];
    const int tid = threadIdx.x;

    if (blockIdx.z == 16) {
        // l-vector GEMV: id -> (batch, 32-col chunk)
        const int id = blockIdx.x * 4 + blockIdx.y;   // 0..31
        const int b = id >> 3;
        const int cc = id & 7;
        float* es = &As[0][0][0];                      // 256 floats
        float* red = &Bs[0][0][0];                     // 128 floats

        const int tgt = (int)x[b * ((NN + 1) * OBSD) + NN * OBSD];
        const float* E = &g_EMB[(b * NN + tgt) * TT];
        for (int i = tid; i < TT; i += 128) es[i] = E[i];
        __syncthreads();

        const int col = cc * 32 + (tid & 31);
        const int ks = (tid >> 5) * 64;
        float s = 0.f;
#pragma unroll 8
        for (int k = 0; k < 64; ++k)
            s = fmaf(es[ks + k], Wl[(ks + k) * TT + col], s);
        red[(tid >> 5) * 32 + (tid & 31)] = s;
        __syncthreads();
        if (tid < 32) {
            int c = cc * 32 + tid;
            float tot = red[tid] + red[32 + tid] + red[64 + tid] + red[96 + tid] + bl[c];
            g_lvec[b * TT + c] = fmaxf(tot, 0.f);
        }
        return;
    }

    const int s = blockIdx.z & 1;
    const int w = (blockIdx.z >> 1) & 1;
    const int b = blockIdx.z >> 2;
    const int kb = s * 128;
    const int r0 = blockIdx.x * 32;
    const int c0 = blockIdx.y * 64;
    const int abase = b * (NN * TT);
    const float* W = (w ? Wh : Wn) + c0;
    const int ty = tid >> 4, tx = tid & 15;

    float acc[4][4] = {};
    mm32x64(
        [&](int kt, int r, int k) {
            int ai = abase + (r0 + r) * TT + kb + kt * 16 + k;
            return g_NEp[0][ai] + g_NEp[1][ai];
        },
        [&](int kt, int kk, int c) { return W[(kb + kt * 16 + kk) * TT + c]; },
        8, acc, tid, As, Bs);

    float* C = &g_CSp[(((s * BB) + b) * 2 + w) * (NN * TT)];
#pragma unroll
    for (int i = 0; i < 4; ++i)
#pragma unroll
        for (int j = 0; j < 4; ++j)
            C[(r0 + ty * 4 + i) * TT + c0 + tx * 4 + j] = acc[i][j];
}

// ---------------------------------------------------------------------------
// K4: combine + trivial epilogue. grid (4 batch, 16 part), 256 thr.
// Part p: w=p&1, cq=(p>>1)&3, row-half rh=p>>3. Block sums its 64 cols over
// 128 rows of relu(P0+P1+bias); LAST block per batch (fence+counter) runs
// the softmax epilogue using precomputed g_lvec (no long GEMV here).
// ---------------------------------------------------------------------------
__global__ void __launch_bounds__(256)
final_kernel(const float* __restrict__ bn, const float* __restrict__ bh,
             const float* __restrict__ Wa, const float* __restrict__ ba,
             float* __restrict__ out)
{
    __shared__ unsigned s_ret;
    const int b = blockIdx.x;
    const int p = blockIdx.y;
    const int w = p & 1;
    const int cq = (p >> 1) & 3;
    const int rh = p >> 3;
    const int t = threadIdx.x;

    {
        const int col = cq * 64 + (t & 63);
        const int rs = rh * 128 + (t >> 6) * 32;
        const float bv = (w ? bh : bn)[col];
        const float* P0 = &g_CSp[(((0 * BB) + b) * 2 + w) * (NN * TT)];
        const float* P1 = &g_CSp[(((1 * BB) + b) * 2 + w) * (NN * TT)];
        float s = 0.f;
#pragma unroll 4
        for (int r = 0; r < 32; ++r) {
            int idx = (rs + r) * TT + col;
            s += fmaxf(P0[idx] + P1[idx] + bv, 0.f);
        }
        float* dst = (w ? g_sumHID : g_sumNH);
        atomicAdd(&dst[b * TT + col], s);
    }

    __threadfence();
    __syncthreads();
    if (t == 0) s_ret = atomicAdd(&g_cnt[b], 1u);
    __syncthreads();
    if (s_ret != 15u) return;
    __threadfence();

    // ---- epilogue for batch b (all inputs precomputed) ----
    __shared__ float av[256];
    __shared__ float prod[256];
    __shared__ float mx[8], sm[8];
    __shared__ float od[32];

    av[t] = g_lvec[b * TT + t] * g_sumNH[b * TT + t];
    __syncthreads();

    if (t < HEADG) {
        float m = -1e30f;
        for (int d = 0; d < DIMG; ++d) m = fmaxf(m, av[d * HEADG + t]);
        float s = 0.f;
        for (int d = 0; d < DIMG; ++d) s += __expf(av[d * HEADG + t] - m);
        mx[t] = m; sm[t] = s;
    }
    __syncthreads();

    int h = t & (HEADG - 1);
    float attn = __expf(av[t] - mx[h]) / sm[h];
    prod[t] = attn * g_sumHID[b * TT + t];
    __syncthreads();

    if (t < DIMG) {
        float s = 0.f;
#pragma unroll
        for (int hh = 0; hh < HEADG; ++hh) s += prod[t * HEADG + hh];
        od[t] = s * (1.0f / HEADG);
    }
    __syncthreads();

    if (t < ACTD) {
        float a = ba[t];
#pragma unroll
        for (int d = 0; d < DIMG; ++d) a = fmaf(od[d], Wa[d * ACTD + t], a);
        out[b * ACTD + t] = a;
    }
}

// ---------------------------------------------------------------------------
extern "C" void kernel_launch(void* const* d_in, const int* in_sizes, int n_in,
                              void* d_out, int out_size)
{
    const float* x   = (const float*)d_in[0];
    const float* adj = (const float*)d_in[1];
    const float* We1 = (const float*)d_in[2];
    const float* be1 = (const float*)d_in[3];
    const float* We2 = (const float*)d_in[4];
    const float* be2 = (const float*)d_in[5];
    const float* Wl  = (const float*)d_in[6];
    const float* bl  = (const float*)d_in[7];
    const float* Wn  = (const float*)d_in[8];
    const float* bn  = (const float*)d_in[9];
    const float* Wh  = (const float*)d_in[10];
    const float* bh  = (const float*)d_in[11];
    const float* Wa  = (const float*)d_in[12];
    const float* ba  = (const float*)d_in[13];
    float* out = (float*)d_out;

    h1emb_kernel<<<dim3(32, 4), 128>>>(x, We1, be1, We2, be2);
    ne_kernel<<<dim3(8, 4, 8), 128>>>(adj);
    colsum_gemm_kernel<<<dim3(8, 4, 17), 128>>>(Wn, Wh, x, Wl, bl);
    final_kernel<<<dim3(BB, 16), 256>>>(bn, bh, Wa, ba, out);
}

// round 17
// speedup vs baseline: 1.2541x; 1.0336x over previous
#include <cuda_runtime.h>

#define BB   4
#define NN   256
#define OBSD 40
#define TT   256
#define DIMG 32
#define HEADG 8
#define ACTD 8

__device__ float g_EMB[BB * NN * TT];
__device__ float g_NEp[2][BB * NN * TT];
__device__ float g_CSp[2 * BB * 2 * NN * TT];   // [s][b][w]
__device__ float g_lvec[BB * TT];
__device__ float g_sumNH[BB * TT];
__device__ float g_sumHID[BB * TT];
__device__ unsigned g_cnt[BB];

// ---------------------------------------------------------------------------
// 32x64 output tile, 128 threads (8x16), 4x4 micro-tile, double-buffered
// k-tiles of 16 (measured-best shape, R6/R11).
// ---------------------------------------------------------------------------
template <class FA, class FB>
__device__ __forceinline__ void mm32x64(FA ldA, FB ldB, int nkt,
                                        float acc[4][4], int tid,
                                        float As[2][16][36], float Bs[2][16][68])
{
    const int ty = tid >> 4, tx = tid & 15;
    {
#pragma unroll
        for (int i = 0; i < 4; ++i) {
            int idx = tid + i * 128;
            As[0][idx & 15][idx >> 4] = ldA(0, idx >> 4, idx & 15);
        }
#pragma unroll
        for (int i = 0; i < 8; ++i) {
            int idx = tid + i * 128;
            Bs[0][idx >> 6][idx & 63] = ldB(0, idx >> 6, idx & 63);
        }
    }
    __syncthreads();
    for (int t = 0; t < nkt; ++t) {
        float ra[4], rb[8];
        if (t + 1 < nkt) {
#pragma unroll
            for (int i = 0; i < 4; ++i) {
                int idx = tid + i * 128;
                ra[i] = ldA(t + 1, idx >> 4, idx & 15);
            }
#pragma unroll
            for (int i = 0; i < 8; ++i) {
                int idx = tid + i * 128;
                rb[i] = ldB(t + 1, idx >> 6, idx & 63);
            }
        }
        int buf = t & 1;
#pragma unroll
        for (int k = 0; k < 16; ++k) {
            float a[4], b[4];
            *(float4*)a = *(const float4*)&As[buf][k][ty * 4];
            *(float4*)b = *(const float4*)&Bs[buf][k][tx * 4];
#pragma unroll
            for (int i = 0; i < 4; ++i)
#pragma unroll
                for (int j = 0; j < 4; ++j) acc[i][j] = fmaf(a[i], b[j], acc[i][j]);
        }
        if (t + 1 < nkt) {
            int nb = buf ^ 1;
#pragma unroll
            for (int i = 0; i < 4; ++i) {
                int idx = tid + i * 128;
                As[nb][idx & 15][idx >> 4] = ra[i];
            }
#pragma unroll
            for (int i = 0; i < 8; ++i) {
                int idx = tid + i * 128;
                Bs[nb][idx >> 6][idx & 63] = rb[i];
            }
            __syncthreads();
        }
    }
}

// ---------------------------------------------------------------------------
// K1: fused h1 + emb. grid (32,4) = 128 blocks, 128 thr.
// ---------------------------------------------------------------------------
__global__ void __launch_bounds__(128)
h1emb_kernel(const float* __restrict__ x,
             const float* __restrict__ We1, const float* __restrict__ be1,
             const float* __restrict__ We2, const float* __restrict__ be2)
{
    __shared__ float H1s[32][260];
    __shared__ float As[2][16][36];
    __shared__ float Bs[2][16][68];
    const int r0 = blockIdx.x * 32;
    const int c0 = blockIdx.y * 64;
    const int tid = threadIdx.x, ty = tid >> 4, tx = tid & 15;

    if (blockIdx.x == 0 && blockIdx.y == 0) {
        for (int i = tid; i < BB * TT; i += 128) {
            g_sumNH[i] = 0.f;
            g_sumHID[i] = 0.f;
        }
        if (tid < BB) g_cnt[tid] = 0u;
    }

    for (int cc = 0; cc < 4; ++cc) {
        float acc[4][4] = {};
        mm32x64(
            [&](int kt, int r, int k) {
                int kg = kt * 16 + k;
                int row = r0 + r, b = row >> 8, n = row & 255;
                return (kg < OBSD) ? x[b * ((NN + 1) * OBSD) + n * OBSD + kg] : 0.f;
            },
            [&](int kt, int kk, int c) {
                int kg = kt * 16 + kk;
                return (kg < OBSD) ? We1[kg * TT + cc * 64 + c] : 0.f;
            },
            3, acc, tid, As, Bs);
        __syncthreads();
#pragma unroll
        for (int i = 0; i < 4; ++i)
#pragma unroll
            for (int j = 0; j < 4; ++j) {
                int c = cc * 64 + tx * 4 + j;
                H1s[ty * 4 + i][c] = fmaxf(acc[i][j] + be1[c], 0.f);
            }
        __syncthreads();
    }

    float acc[4][4] = {};
    mm32x64(
        [&](int kt, int r, int k) { return H1s[r][kt * 16 + k]; },
        [&](int kt, int kk, int c) { return We2[(kt * 16 + kk) * TT + c0 + c]; },
        16, acc, tid, As, Bs);

#pragma unroll
    for (int i = 0; i < 4; ++i)
#pragma unroll
        for (int j = 0; j < 4; ++j) {
            int c = c0 + tx * 4 + j;
            g_EMB[(r0 + ty * 4 + i) * TT + c] = fmaxf(acc[i][j] + be2[c], 0.f);
        }
}

// ---------------------------------------------------------------------------
// K2: NEp[s][b] = adj @ EMB[b] over K-half s. grid (8,4,8) = 256 blocks.
// ---------------------------------------------------------------------------
__global__ void __launch_bounds__(128)
ne_kernel(const float* __restrict__ adj)
{
    __shared__ float As[2][16][36];
    __shared__ float Bs[2][16][68];
    const int b = blockIdx.z >> 1;
    const int s = blockIdx.z & 1;
    const int kb = s * 128;
    const int r0 = blockIdx.x * 32;
    const int c0 = blockIdx.y * 64;
    const int ebase = b * (NN * TT);
    const int tid = threadIdx.x, ty = tid >> 4, tx = tid & 15;

    float acc[4][4] = {};
    mm32x64(
        [&](int kt, int r, int k) { return adj[(r0 + r) * NN + kb + kt * 16 + k]; },
        [&](int kt, int kk, int c) {
            return g_EMB[ebase + (kb + kt * 16 + kk) * TT + c0 + c];
        },
        8, acc, tid, As, Bs);

    float* C = &g_NEp[s][ebase];
#pragma unroll
    for (int i = 0; i < 4; ++i)
#pragma unroll
        for (int j = 0; j < 4; ++j)
            C[(r0 + ty * 4 + i) * TT + c0 + tx * 4 + j] = acc[i][j];
}

// ---------------------------------------------------------------------------
// K3: z<16: CSp[s][b][w] = NE[b] @ W_w over K-half s (512 blocks).
// z==16: 32 extra blocks compute l[b] = relu(emb[b,tgt] @ Wl + bl),
// hidden under the colsum GEMM. grid (8,4,17).
// ---------------------------------------------------------------------------
__global__ void __launch_bounds__(128)
colsum_gemm_kernel(const float* __restrict__ Wn, const float* __restrict__ Wh,
                   const float* __restrict__ x,
                   const float* __restrict__ Wl, const float* __restrict__ bl)
{
    __shared__ float As[2][16][36];
    __shared__ float Bs[2][16][68];
    const int tid = threadIdx.x;

    if (blockIdx.z == 16) {
        const int id = blockIdx.x * 4 + blockIdx.y;   // 0..31
        const int b = id >> 3;
        const int cc = id & 7;
        float* es = &As[0][0][0];                      // 256 floats
        float* red = &Bs[0][0][0];                     // 128 floats

        const int tgt = (int)x[b * ((NN + 1) * OBSD) + NN * OBSD];
        const float* E = &g_EMB[(b * NN + tgt) * TT];
        for (int i = tid; i < TT; i += 128) es[i] = E[i];
        __syncthreads();

        const int col = cc * 32 + (tid & 31);
        const int ks = (tid >> 5) * 64;
        float s = 0.f;
#pragma unroll 8
        for (int k = 0; k < 64; ++k)
            s = fmaf(es[ks + k], Wl[(ks + k) * TT + col], s);
        red[(tid >> 5) * 32 + (tid & 31)] = s;
        __syncthreads();
        if (tid < 32) {
            int c = cc * 32 + tid;
            float tot = red[tid] + red[32 + tid] + red[64 + tid] + red[96 + tid] + bl[c];
            g_lvec[b * TT + c] = fmaxf(tot, 0.f);
        }
        return;
    }

    const int s = blockIdx.z & 1;
    const int w = (blockIdx.z >> 1) & 1;
    const int b = blockIdx.z >> 2;
    const int kb = s * 128;
    const int r0 = blockIdx.x * 32;
    const int c0 = blockIdx.y * 64;
    const int abase = b * (NN * TT);
    const float* W = (w ? Wh : Wn) + c0;
    const int ty = tid >> 4, tx = tid & 15;

    float acc[4][4] = {};
    mm32x64(
        [&](int kt, int r, int k) {
            int ai = abase + (r0 + r) * TT + kb + kt * 16 + k;
            return g_NEp[0][ai] + g_NEp[1][ai];
        },
        [&](int kt, int kk, int c) { return W[(kb + kt * 16 + kk) * TT + c]; },
        8, acc, tid, As, Bs);

    float* C = &g_CSp[(((s * BB) + b) * 2 + w) * (NN * TT)];
#pragma unroll
    for (int i = 0; i < 4; ++i)
#pragma unroll
        for (int j = 0; j < 4; ++j)
            C[(r0 + ty * 4 + i) * TT + c0 + tx * 4 + j] = acc[i][j];
}

// ---------------------------------------------------------------------------
// K4: combine + trivial epilogue. grid (4 batch, 64 part), 256 thr.
// Part p: w=p&1, rh=p>>1 (32 row-chunks of 8). Block covers all 256 cols:
// thread t -> sub-rowpair (t>>6), col4 = (t&63)*4. float4 loads of P0/P1,
// relu-sum of 2 rows; smem reduce over the 4 sub groups; ONE atomic per col.
// LAST block per batch (fence+counter, 64 parts) runs the softmax epilogue
// from precomputed g_lvec.
// ---------------------------------------------------------------------------
__global__ void __launch_bounds__(256)
final_kernel(const float* __restrict__ bn, const float* __restrict__ bh,
             const float* __restrict__ Wa, const float* __restrict__ ba,
             float* __restrict__ out)
{
    __shared__ float red[4][TT];
    __shared__ unsigned s_ret;
    const int b = blockIdx.x;
    const int p = blockIdx.y;
    const int w = p & 1;
    const int rh = p >> 1;          // 0..31
    const int t = threadIdx.x;

    {
        const int sub = t >> 6;             // 0..3 -> row pair
        const int c4 = (t & 63) * 4;        // col base
        const int r0 = rh * 8 + sub * 2;
        const float* P0 = &g_CSp[(((0 * BB) + b) * 2 + w) * (NN * TT)];
        const float* P1 = &g_CSp[(((1 * BB) + b) * 2 + w) * (NN * TT)];
        const float4 bv = *(const float4*)&(w ? bh : bn)[c4];

        float4 a0 = *(const float4*)&P0[r0 * TT + c4];
        float4 a1 = *(const float4*)&P1[r0 * TT + c4];
        float4 b0 = *(const float4*)&P0[(r0 + 1) * TT + c4];
        float4 b1 = *(const float4*)&P1[(r0 + 1) * TT + c4];

        red[sub][c4 + 0] = fmaxf(a0.x + a1.x + bv.x, 0.f) + fmaxf(b0.x + b1.x + bv.x, 0.f);
        red[sub][c4 + 1] = fmaxf(a0.y + a1.y + bv.y, 0.f) + fmaxf(b0.y + b1.y + bv.y, 0.f);
        red[sub][c4 + 2] = fmaxf(a0.z + a1.z + bv.z, 0.f) + fmaxf(b0.z + b1.z + bv.z, 0.f);
        red[sub][c4 + 3] = fmaxf(a0.w + a1.w + bv.w, 0.f) + fmaxf(b0.w + b1.w + bv.w, 0.f);
    }
    __syncthreads();
    {
        float tot = red[0][t] + red[1][t] + red[2][t] + red[3][t];
        float* dst = (w ? g_sumHID : g_sumNH);
        atomicAdd(&dst[b * TT + t], tot);
    }

    __threadfence();
    __syncthreads();
    if (t == 0) s_ret = atomicAdd(&g_cnt[b], 1u);
    __syncthreads();
    if (s_ret != 63u) return;
    __threadfence();

    // ---- epilogue for batch b (all inputs precomputed) ----
    __shared__ float av[256];
    __shared__ float prod[256];
    __shared__ float mx[8], sm[8];
    __shared__ float od[32];

    av[t] = g_lvec[b * TT + t] * g_sumNH[b * TT + t];
    __syncthreads();

    if (t < HEADG) {
        float m = -1e30f;
        for (int d = 0; d < DIMG; ++d) m = fmaxf(m, av[d * HEADG + t]);
        float s = 0.f;
        for (int d = 0; d < DIMG; ++d) s += __expf(av[d * HEADG + t] - m);
        mx[t] = m; sm[t] = s;
    }
    __syncthreads();

    int h = t & (HEADG - 1);
    float attn = __expf(av[t] - mx[h]) / sm[h];
    prod[t] = attn * g_sumHID[b * TT + t];
    __syncthreads();

    if (t < DIMG) {
        float s = 0.f;
#pragma unroll
        for (int hh = 0; hh < HEADG; ++hh) s += prod[t * HEADG + hh];
        od[t] = s * (1.0f / HEADG);
    }
    __syncthreads();

    if (t < ACTD) {
        float a = ba[t];
#pragma unroll
        for (int d = 0; d < DIMG; ++d) a = fmaf(od[d], Wa[d * ACTD + t], a);
        out[b * ACTD + t] = a;
    }
}

// ---------------------------------------------------------------------------
extern "C" void kernel_launch(void* const* d_in, const int* in_sizes, int n_in,
                              void* d_out, int out_size)
{
    const float* x   = (const float*)d_in[0];
    const float* adj = (const float*)d_in[1];
    const float* We1 = (const float*)d_in[2];
    const float* be1 = (const float*)d_in[3];
    const float* We2 = (const float*)d_in[4];
    const float* be2 = (const float*)d_in[5];
    const float* Wl  = (const float*)d_in[6];
    const float* bl  = (const float*)d_in[7];
    const float* Wn  = (const float*)d_in[8];
    const float* bn  = (const float*)d_in[9];
    const float* Wh  = (const float*)d_in[10];
    const float* bh  = (const float*)d_in[11];
    const float* Wa  = (const float*)d_in[12];
    const float* ba  = (const float*)d_in[13];
    float* out = (float*)d_out;

    h1emb_kernel<<<dim3(32, 4), 128>>>(x, We1, be1, We2, be2);
    ne_kernel<<<dim3(8, 4, 8), 128>>>(adj);
    colsum_gemm_kernel<<<dim3(8, 4, 17), 128>>>(Wn, Wh, x, Wl, bl);
    final_kernel<<<dim3(BB, 64), 256>>>(bn, bh, Wa, ba, out);
}